// round 10
// baseline (speedup 1.0000x reference)
#include <cuda_runtime.h>
#include <cuda_bf16.h>
#include <stdint.h>
#include <math.h>

#define NB   16
#define NC   512
#define NN   1024
#define NG   8
#define NH   8
#define ND   64
#define KTOT 512
#define CS   (1.44269504f / 64.0f)   // log2(e)/64 folded into q

// ---------------- scratch (device globals; no allocation) ----------------
__device__ unsigned short g_xnt[(size_t)NB * NN * NC];        // bf16 [b][n][c]
__device__ unsigned short g_qkvt[(size_t)NB * NN * 3 * NC];   // bf16 [b][n][o]
__device__ unsigned short g_att[(size_t)NB * NN * NC];        // bf16 [b][n][c]
__device__ unsigned short g_wq[3 * NC * NC];                  // bf16 [o][c]
__device__ unsigned short g_wp[NC * NC];                      // bf16 [c][c]

// ---------------- PTX helpers (plain sm_80/sm_90 features only) -----------
__device__ __forceinline__ uint32_t smem_u32(const void* p) {
    uint32_t a;
    asm("{ .reg .u64 t; cvta.to.shared.u64 t, %1; cvt.u32.u64 %0, t; }"
        : "=r"(a) : "l"(p));
    return a;
}
__device__ __forceinline__ void cp16(uint32_t s, const void* g) {
    asm volatile("cp.async.cg.shared.global [%0], [%1], 16;" :: "r"(s), "l"(g));
}
__device__ __forceinline__ void cp_commit() {
    asm volatile("cp.async.commit_group;" ::: "memory");
}
__device__ __forceinline__ void ldm4(uint32_t* r, uint32_t addr) {
    asm volatile("ldmatrix.sync.aligned.m8n8.x4.shared.b16 {%0,%1,%2,%3}, [%4];"
                 : "=r"(r[0]), "=r"(r[1]), "=r"(r[2]), "=r"(r[3]) : "r"(addr));
}
__device__ __forceinline__ void ldm4t(uint32_t* r, uint32_t addr) {
    asm volatile("ldmatrix.sync.aligned.m8n8.x4.trans.shared.b16 {%0,%1,%2,%3}, [%4];"
                 : "=r"(r[0]), "=r"(r[1]), "=r"(r[2]), "=r"(r[3]) : "r"(addr));
}
__device__ __forceinline__ void mma16816(float* c, const uint32_t* a,
                                         const uint32_t* b) {
    asm volatile(
        "mma.sync.aligned.m16n8k16.row.col.f32.bf16.bf16.f32 "
        "{%0,%1,%2,%3}, {%4,%5,%6,%7}, {%8,%9}, {%0,%1,%2,%3};"
        : "+f"(c[0]), "+f"(c[1]), "+f"(c[2]), "+f"(c[3])
        : "r"(a[0]), "r"(a[1]), "r"(a[2]), "r"(a[3]), "r"(b[0]), "r"(b[1]));
}
__device__ __forceinline__ uint32_t packbf(float hi, float lo) {
    uint32_t r;
    asm("cvt.rn.bf16x2.f32 %0, %1, %2;" : "=r"(r) : "f"(hi), "f"(lo));
    return r;
}
__device__ __forceinline__ uint32_t ex2bf2(uint32_t x) {
    uint32_t r;
    asm("ex2.approx.ftz.bf16x2 %0, %1;" : "=r"(r) : "r"(x));
    return r;
}

// ---------------------------------------------------------------------------
// fp32 -> bf16 weight convert (both weights in one launch)
// ---------------------------------------------------------------------------
__global__ void cvt_kernel(const float* __restrict__ w1, __nv_bfloat16* __restrict__ o1, int n1,
                           const float* __restrict__ w2, __nv_bfloat16* __restrict__ o2, int n2) {
    int i = blockIdx.x * blockDim.x + threadIdx.x;
    if (i < n1) o1[i] = __float2bfloat16(w1[i]);
    else if (i < n1 + n2) o2[i - n1] = __float2bfloat16(w2[i - n1]);
}

// ---------------------------------------------------------------------------
// GroupNorm -> transposed bf16: xnt[b][n][c]  (1024 threads/block)
// ---------------------------------------------------------------------------
__global__ void gn_kernel(const float* __restrict__ x,
                          const float* __restrict__ w,
                          const float* __restrict__ bb,
                          __nv_bfloat16* __restrict__ outp) {
    const int GSIZE = (NC / NG) * NN;  // 65536
    int blk = blockIdx.x;
    int g = blk & (NG - 1), b = blk >> 3;
    const float* base = x + (size_t)blk * GSIZE;

    float s = 0.f, sq = 0.f;
    const float4* b4 = (const float4*)base;
    for (int i = threadIdx.x; i < GSIZE / 4; i += blockDim.x) {
        float4 v = b4[i];
        s  += v.x + v.y + v.z + v.w;
        sq += v.x * v.x + v.y * v.y + v.z * v.z + v.w * v.w;
    }
    __shared__ float rs[32], rq[32];
    #pragma unroll
    for (int o = 16; o; o >>= 1) {
        s  += __shfl_xor_sync(0xffffffffu, s, o);
        sq += __shfl_xor_sync(0xffffffffu, sq, o);
    }
    int wid = threadIdx.x >> 5, lane = threadIdx.x & 31;
    if (lane == 0) { rs[wid] = s; rq[wid] = sq; }
    __syncthreads();
    if (wid == 0) {
        s  = (lane < (int)(blockDim.x >> 5)) ? rs[lane] : 0.f;
        sq = (lane < (int)(blockDim.x >> 5)) ? rq[lane] : 0.f;
        #pragma unroll
        for (int o = 16; o; o >>= 1) {
            s  += __shfl_xor_sync(0xffffffffu, s, o);
            sq += __shfl_xor_sync(0xffffffffu, sq, o);
        }
        if (lane == 0) { rs[0] = s; rq[0] = sq; }
    }
    __syncthreads();
    float mean = rs[0] / (float)GSIZE;
    float var  = rq[0] / (float)GSIZE - mean * mean;
    float rstd = rsqrtf(var + 1e-5f);

    __shared__ float sgw[64], sgb[64];
    __shared__ float tile[64][65];
    if (threadIdx.x < 64) {
        float gw = w[g * 64 + threadIdx.x] * rstd;
        sgw[threadIdx.x] = gw;
        sgb[threadIdx.x] = bb[g * 64 + threadIdx.x] - mean * gw;
    }
    for (int nt = 0; nt < 16; nt++) {
        __syncthreads();
        int n0t = nt * 64;
        #pragma unroll
        for (int it = 0; it < 4; it++) {
            int e = threadIdx.x + it * 1024;
            int c = e >> 6, j = e & 63;
            tile[c][j] = base[c * NN + n0t + j] * sgw[c] + sgb[c];
        }
        __syncthreads();
        #pragma unroll
        for (int it = 0; it < 4; it++) {
            int e = threadIdx.x + it * 1024;
            int j = e >> 6, c = e & 63;
            outp[((size_t)b * NN + n0t + j) * NC + g * 64 + c] =
                __float2bfloat16(tile[c][j]);
        }
    }
}

// ---------------------------------------------------------------------------
// bf16 mma.sync GEMM: 128x128 tile, BK=32, 128 threads (2x2 warps of 64x64),
// 4-stage cp.async ring (dist 2), 2 CTAs/SM. ldm4:MMA ratio = 4.0.
// QKV epilogue scales q-channel outputs (col < NC) by CS for attention.
// ---------------------------------------------------------------------------
#define BM 128
#define BN 128
#define BK 32
#define SROW 80
#define OFF_B (BM * SROW)
#define STG   (OFF_B + BN * SROW)          // 20480
#define GEMM_SMEM (4 * STG)                // 81920

__device__ __forceinline__ void g_load_stage(
    uint32_t dst, int tid, const __nv_bfloat16* __restrict__ A,
    const __nv_bfloat16* __restrict__ B) {
    #pragma unroll
    for (int u = 0; u < 4; u++) {
        int idx = tid + u * 128;
        int r = idx >> 2, seg = idx & 3;
        uint32_t so = r * SROW + seg * 16;
        size_t go = (size_t)r * KTOT + seg * 8;
        cp16(dst + so, A + go);
        cp16(dst + OFF_B + so, B + go);
    }
}

template <bool PROJ>
__global__ __launch_bounds__(128, 2)
void mma_gemm(const __nv_bfloat16* __restrict__ Ag, size_t aStride,
              const __nv_bfloat16* __restrict__ Bg, size_t bStride,
              const float* __restrict__ bias,
              const float* __restrict__ resid,
              float* __restrict__ outF,
              __nv_bfloat16* __restrict__ outB) {
    extern __shared__ char smem[];
    uint32_t sb = smem_u32(smem);
    int tid = threadIdx.x, wid = tid >> 5, lane = tid & 31;
    int bz = blockIdx.z, m0 = blockIdx.y * BM, n0 = blockIdx.x * BN;

    int m0w = (wid & 1) * 64;   // 2 warps in m
    int n0w = (wid >> 1) * 64;  // 2 warps in n

    int a_r = ((lane >> 3) & 1) * 8 + (lane & 7);
    int a_k = (lane >> 4);
    int b_r = (lane >> 4) * 8 + (lane & 7);
    int b_k = (lane >> 3) & 1;

    const __nv_bfloat16* A0 = Ag + (size_t)bz * aStride + (size_t)m0 * KTOT;
    const __nv_bfloat16* B0 = Bg + (size_t)bz * bStride + (size_t)n0 * KTOT;

    float acc[4][8][4];
    #pragma unroll
    for (int mi = 0; mi < 4; mi++)
        #pragma unroll
        for (int ni = 0; ni < 8; ni++)
            #pragma unroll
            for (int e = 0; e < 4; e++) acc[mi][ni][e] = 0.f;

    g_load_stage(sb, tid, A0, B0);
    cp_commit();
    g_load_stage(sb + STG, tid, A0 + BK, B0 + BK);
    cp_commit();

    const int NSTG = KTOT / BK;  // 16
    for (int i = 0; i < NSTG; i++) {
        if (i + 2 < NSTG) {
            int k0 = (i + 2) * BK;
            g_load_stage(sb + ((i + 2) & 3) * STG, tid, A0 + k0, B0 + k0);
            cp_commit();
            asm volatile("cp.async.wait_group 2;" ::: "memory");
        } else if (i == NSTG - 2) {
            asm volatile("cp.async.wait_group 1;" ::: "memory");
        } else {
            asm volatile("cp.async.wait_group 0;" ::: "memory");
        }
        __syncthreads();

        uint32_t sbase = sb + (i & 3) * STG;
        uint32_t aBase = sbase + (m0w + a_r) * SROW + a_k * 16;
        uint32_t bBase = sbase + OFF_B + (n0w + b_r) * SROW + b_k * 16;

        #pragma unroll
        for (int s = 0; s < 2; s++) {
            uint32_t ks = s * 32;
            uint32_t a[4][4], bfr[8][2];
            #pragma unroll
            for (int mi = 0; mi < 4; mi++)
                ldm4(a[mi], aBase + mi * (16 * SROW) + ks);
            #pragma unroll
            for (int nj = 0; nj < 4; nj++)
                ldm4(&bfr[nj * 2][0], bBase + nj * (16 * SROW) + ks);
            #pragma unroll
            for (int mi = 0; mi < 4; mi++)
                #pragma unroll
                for (int ni = 0; ni < 8; ni++)
                    mma16816(acc[mi][ni], a[mi], bfr[ni]);
        }
    }

    int g = lane >> 2, t = lane & 3;
    if (PROJ) {
        #pragma unroll
        for (int mi = 0; mi < 4; mi++) {
            int row0 = m0 + m0w + mi * 16 + g, row1 = row0 + 8;
            float bi0 = bias[row0], bi1 = bias[row1];
            float* o0 = outF + ((size_t)bz * NC + row0) * NN + n0 + n0w + t * 2;
            float* o1 = outF + ((size_t)bz * NC + row1) * NN + n0 + n0w + t * 2;
            const float* r0 = resid + ((size_t)bz * NC + row0) * NN + n0 + n0w + t * 2;
            const float* r1 = resid + ((size_t)bz * NC + row1) * NN + n0 + n0w + t * 2;
            #pragma unroll
            for (int ni = 0; ni < 8; ni++) {
                float2 a0 = *(const float2*)(r0 + ni * 8);
                float2 a1 = *(const float2*)(r1 + ni * 8);
                float2 v0, v1;
                v0.x = acc[mi][ni][0] + bi0 + a0.x;
                v0.y = acc[mi][ni][1] + bi0 + a0.y;
                v1.x = acc[mi][ni][2] + bi1 + a1.x;
                v1.y = acc[mi][ni][3] + bi1 + a1.y;
                *(float2*)(o0 + ni * 8) = v0;
                *(float2*)(o1 + ni * 8) = v1;
            }
        }
    } else {
        #pragma unroll
        for (int mi = 0; mi < 4; mi++) {
            int row0 = m0 + m0w + mi * 16 + g, row1 = row0 + 8;
            uint32_t* o0 = (uint32_t*)(outB + ((size_t)bz * NN + row0) * (3 * NC));
            uint32_t* o1 = (uint32_t*)(outB + ((size_t)bz * NN + row1) * (3 * NC));
            #pragma unroll
            for (int ni = 0; ni < 8; ni++) {
                int col = n0 + n0w + ni * 8 + t * 2;
                float sc = (col < NC) ? CS : 1.0f;  // fold softmax scale into q
                float b0 = bias[col], b1 = bias[col + 1];
                o0[col >> 1] = packbf((acc[mi][ni][1] + b1) * sc,
                                      (acc[mi][ni][0] + b0) * sc);
                o1[col >> 1] = packbf((acc[mi][ni][3] + b1) * sc,
                                      (acc[mi][ni][2] + b0) * sc);
            }
        }
    }
}

// ---------------------------------------------------------------------------
// bf16 mma.sync flash attention, shift-free softmax, 2 m-frags per warp:
// 128 threads / CTA (4 warps x 32 q rows), 2 CTAs/SM.
// ---------------------------------------------------------------------------
#define AROW 144
#define Q_SZ (128 * AROW)                 // 18432
#define KV_T (64 * AROW)                  // 9216
#define ATTN_SMEM (Q_SZ + 8 * KV_T)       // 92160

__global__ __launch_bounds__(128, 2)
void attn_kernel(const __nv_bfloat16* __restrict__ qkvt,
                 __nv_bfloat16* __restrict__ att) {
    extern __shared__ char smem[];
    uint32_t sb = smem_u32(smem);
    int tid = threadIdx.x, wid = tid >> 5, lane = tid & 31;
    int g = lane >> 2, t = lane & 3;
    int qb = blockIdx.x, h = blockIdx.y, b = blockIdx.z;

    const __nv_bfloat16* Qg = qkvt + ((size_t)b * NN + qb * 128) * (3 * NC) + h * ND;
    const __nv_bfloat16* Kg = qkvt + (size_t)b * NN * (3 * NC) + NC + h * ND;
    const __nv_bfloat16* Vg = Kg + NC;

    uint32_t kv = sb + Q_SZ;

    // group 0: Q (128 x 64)
    #pragma unroll
    for (int u = 0; u < 8; u++) {
        int idx = tid + u * 128;
        int r = idx >> 3, seg = idx & 7;
        cp16(sb + r * AROW + seg * 16, Qg + (size_t)r * (3 * NC) + seg * 8);
    }
    cp_commit();
    // groups 1,2: KV tiles 0 and 1
    #pragma unroll
    for (int p = 0; p < 2; p++) {
        uint32_t buf = kv + p * (2 * KV_T);
        #pragma unroll
        for (int u = 0; u < 4; u++) {
            int idx = tid + u * 128;
            int r = idx >> 3, seg = idx & 7;
            size_t grow = (size_t)(p * 64 + r) * (3 * NC) + seg * 8;
            cp16(buf + r * AROW + seg * 16, Kg + grow);
            cp16(buf + KV_T + r * AROW + seg * 16, Vg + grow);
        }
        cp_commit();
    }

    asm volatile("cp.async.wait_group 2;" ::: "memory");
    __syncthreads();
    int a_r = ((lane >> 3) & 1) * 8 + (lane & 7);
    int a_k = (lane >> 4);
    uint32_t qf[2][4][4];
    #pragma unroll
    for (int mi = 0; mi < 2; mi++) {
        uint32_t qaddr = sb + (wid * 32 + mi * 16 + a_r) * AROW + a_k * 16;
        #pragma unroll
        for (int kd = 0; kd < 4; kd++) ldm4(qf[mi][kd], qaddr + kd * 32);
    }

    float o[2][8][4];
    float osum[2][4];
    #pragma unroll
    for (int mi = 0; mi < 2; mi++) {
        #pragma unroll
        for (int nt = 0; nt < 8; nt++)
            #pragma unroll
            for (int e = 0; e < 4; e++) o[mi][nt][e] = 0.f;
        #pragma unroll
        for (int e = 0; e < 4; e++) osum[mi][e] = 0.f;
    }
    const uint32_t ones2 = 0x3F803F80u;  // bf16x2 {1.0, 1.0}
    uint32_t onesfrag[2] = {ones2, ones2};

    int b_r = (lane >> 4) * 8 + (lane & 7);
    int b_k = (lane >> 3) & 1;

    for (int mt = 0; mt < 16; mt++) {
        if (mt + 2 < 16) {
            uint32_t nb = kv + ((mt + 2) & 3) * (2 * KV_T);
            #pragma unroll
            for (int u = 0; u < 4; u++) {
                int idx = tid + u * 128;
                int r = idx >> 3, seg = idx & 7;
                size_t grow = (size_t)((mt + 2) * 64 + r) * (3 * NC) + seg * 8;
                cp16(nb + r * AROW + seg * 16, Kg + grow);
                cp16(nb + KV_T + r * AROW + seg * 16, Vg + grow);
            }
            cp_commit();
            asm volatile("cp.async.wait_group 2;" ::: "memory");
        } else if (mt == 14) {
            asm volatile("cp.async.wait_group 1;" ::: "memory");
        } else {
            asm volatile("cp.async.wait_group 0;" ::: "memory");
        }
        __syncthreads();

        uint32_t kbuf = kv + (mt & 3) * (2 * KV_T);
        uint32_t vbuf = kbuf + KV_T;

        // ---- S = Q K^T, both m-frags share K fragments ----
        float c[2][8][4];
        #pragma unroll
        for (int mi = 0; mi < 2; mi++)
            #pragma unroll
            for (int nt = 0; nt < 8; nt++)
                #pragma unroll
                for (int e = 0; e < 4; e++) c[mi][nt][e] = 0.f;
        #pragma unroll
        for (int kd = 0; kd < 4; kd++) {
            uint32_t bfr[8][2];
            uint32_t kaddr = kbuf + b_r * AROW + kd * 32 + b_k * 16;
            #pragma unroll
            for (int nj = 0; nj < 4; nj++)
                ldm4(&bfr[nj * 2][0], kaddr + nj * (16 * AROW));
            #pragma unroll
            for (int mi = 0; mi < 2; mi++)
                #pragma unroll
                for (int nt = 0; nt < 8; nt++)
                    mma16816(c[mi][nt], qf[mi][kd], bfr[nt]);
        }

        // ---- P = exp2(S), packed bf16x2 ----
        uint32_t p01[2][8], p23[2][8];
        #pragma unroll
        for (int mi = 0; mi < 2; mi++)
            #pragma unroll
            for (int nt = 0; nt < 8; nt++) {
                p01[mi][nt] = ex2bf2(packbf(c[mi][nt][1], c[mi][nt][0]));
                p23[mi][nt] = ex2bf2(packbf(c[mi][nt][3], c[mi][nt][2]));
            }

        // ---- O += P V, row sums += P @ ones; V frags shared across mi ----
        #pragma unroll
        for (int j = 0; j < 4; j++) {
            uint32_t vb[8][2];
            uint32_t vaddr = vbuf + (j * 16 + a_r) * AROW + a_k * 16;
            #pragma unroll
            for (int nj = 0; nj < 4; nj++)
                ldm4t(&vb[nj * 2][0], vaddr + nj * 32);
            #pragma unroll
            for (int mi = 0; mi < 2; mi++) {
                uint32_t pa[4];
                pa[0] = p01[mi][2 * j];
                pa[1] = p23[mi][2 * j];
                pa[2] = p01[mi][2 * j + 1];
                pa[3] = p23[mi][2 * j + 1];
                mma16816(osum[mi], pa, onesfrag);
                #pragma unroll
                for (int nt = 0; nt < 8; nt++)
                    mma16816(o[mi][nt], pa, vb[nt]);
            }
        }
    }

    // ---- epilogue ----
    #pragma unroll
    for (int mi = 0; mi < 2; mi++) {
        float inv0 = 1.0f / osum[mi][0], inv1 = 1.0f / osum[mi][2];
        int q0 = qb * 128 + wid * 32 + mi * 16 + g, q1 = q0 + 8;
        uint32_t* O0 = (uint32_t*)(att + ((size_t)b * NN + q0) * NC + h * ND);
        uint32_t* O1 = (uint32_t*)(att + ((size_t)b * NN + q1) * NC + h * ND);
        #pragma unroll
        for (int nt = 0; nt < 8; nt++) {
            int col = nt * 8 + t * 2;
            O0[col >> 1] = packbf(o[mi][nt][1] * inv0, o[mi][nt][0] * inv0);
            O1[col >> 1] = packbf(o[mi][nt][3] * inv1, o[mi][nt][2] * inv1);
        }
    }
}

// ---------------------------------------------------------------------------
extern "C" void kernel_launch(void* const* d_in, const int* in_sizes, int n_in,
                              void* d_out, int out_size) {
    const float* x      = (const float*)d_in[0];
    const float* norm_w = (const float*)d_in[1];
    const float* norm_b = (const float*)d_in[2];
    const float* qkv_w  = (const float*)d_in[3];
    const float* qkv_b  = (const float*)d_in[4];
    const float* proj_w = (const float*)d_in[5];
    const float* proj_b = (const float*)d_in[6];
    float* out = (float*)d_out;

    __nv_bfloat16 *xnt, *qkvt, *attb, *wq, *wp;
    cudaGetSymbolAddress((void**)&xnt, g_xnt);
    cudaGetSymbolAddress((void**)&qkvt, g_qkvt);
    cudaGetSymbolAddress((void**)&attb, g_att);
    cudaGetSymbolAddress((void**)&wq, g_wq);
    cudaGetSymbolAddress((void**)&wp, g_wp);

    cudaFuncSetAttribute(mma_gemm<false>, cudaFuncAttributeMaxDynamicSharedMemorySize, GEMM_SMEM);
    cudaFuncSetAttribute(mma_gemm<true>,  cudaFuncAttributeMaxDynamicSharedMemorySize, GEMM_SMEM);
    cudaFuncSetAttribute(attn_kernel, cudaFuncAttributeMaxDynamicSharedMemorySize, ATTN_SMEM);

    // 0) weights -> bf16 (single launch)
    int ntot = 3 * NC * NC + NC * NC;
    cvt_kernel<<<(ntot + 255) / 256, 256>>>(qkv_w, wq, 3 * NC * NC, proj_w, wp, NC * NC);
    // 1) GroupNorm -> xnt bf16 [b][n][c]
    gn_kernel<<<NB * NG, 1024>>>(x, norm_w, norm_b, xnt);
    // 2) QKV GEMM (q cols pre-scaled by CS): qkvt[b][n][o] bf16
    mma_gemm<false><<<dim3((3 * NC) / BN, NN / BM, NB), 128, GEMM_SMEM>>>(
        xnt, (size_t)NN * KTOT, wq, 0, qkv_b, nullptr, nullptr, qkvt);
    // 3) flash attention -> att[b][n][c] bf16
    attn_kernel<<<dim3(NN / 128, NH, NB), 128, ATTN_SMEM>>>(qkvt, attb);
    // 4) proj GEMM + bias + residual -> out fp32 [b][c][n]
    mma_gemm<true><<<dim3(NN / BN, NC / BM, NB), 128, GEMM_SMEM>>>(
        wp, 0, attb, (size_t)NN * KTOT, proj_b, x, out, nullptr);
}